// round 6
// baseline (speedup 1.0000x reference)
#include <cuda_runtime.h>

typedef unsigned long long u64;

#define NTHREADS 256
#define GRID_BLOCKS 2048   // 1048576 elems / (2 per thread * 256)
#define SCRP 18            // scratch pitch (floats): even -> 8B-aligned LDS.64

// ---------- packed f32x2 + approx-math helpers ----------
__device__ __forceinline__ u64 f2fma(u64 a, u64 b, u64 c) {
    u64 d; asm("fma.rn.f32x2 %0, %1, %2, %3;" : "=l"(d) : "l"(a), "l"(b), "l"(c)); return d;
}
__device__ __forceinline__ u64 pk2(float lo, float hi) {
    u64 d; asm("mov.b64 %0, {%1,%2};" : "=l"(d) : "f"(lo), "f"(hi)); return d;
}
__device__ __forceinline__ float hsum(u64 a) {   // lo + hi
    float lo, hi;
    asm("mov.b64 {%0,%1}, %2;" : "=f"(lo), "=f"(hi) : "l"(a));
    return lo + hi;
}
__device__ __forceinline__ float ex2f(float x) {
    float y; asm("ex2.approx.f32 %0, %1;" : "=f"(y) : "f"(x)); return y;
}
__device__ __forceinline__ float rcpf(float x) {
    float y; asm("rcp.approx.f32 %0, %1;" : "=f"(y) : "f"(x)); return y;
}
__device__ __forceinline__ float sigmoidf_(float a) {
    return rcpf(1.0f + ex2f(-1.4426950408889634f * a));
}
__device__ __forceinline__ float tanhf_(float a) {
    return fmaf(2.0f, rcpf(1.0f + ex2f(-2.8853900817779268f * a)), -1.0f);
}

// ---------- kernel ----------
// B=1048576, T=4, I=2, H=16
// out layout: [hidden_table B*T*H][sum_logits B*T][carry B][output_logits B*5]

__global__ __launch_bounds__(NTHREADS, 2)
void gru_adder_kernel(const float* __restrict__ x,
                      const float* __restrict__ wih,   // [48,2]
                      const float* __restrict__ whh,   // [48,16]
                      const float* __restrict__ bih,   // [48]
                      const float* __restrict__ bhh,   // [48]
                      const float* __restrict__ wsum,  // [1,16]
                      const float* __restrict__ bsum,  // [1]
                      const float* __restrict__ wcar,  // [1,16]
                      const float* __restrict__ bcar,  // [1]
                      float* __restrict__ out)
{
    extern __shared__ __align__(16) char smem_raw[];
    u64*   s_wih   = (u64*)smem_raw;          // 48  (wih[j][0], wih[j][1])
    u64*   s_whh   = s_wih + 48;              // 384 [j][q] = (whh[j][2q], whh[j][2q+1])
    u64*   s_wsumP = s_whh + 384;             // 8
    u64*   s_wcarP = s_wsumP + 8;             // 8
    float* s_brz   = (float*)(s_wcarP + 8);   // 32  b_ih+b_hh (r,z rows)
    float* s_bin   = s_brz + 32;              // 16
    float* s_bhn   = s_bin + 16;              // 16
    float* s_bs    = s_bhn + 16;              // 2 (+2 pad)
    float* s_nA    = s_bs + 4;                // [tid][k] pitch 18
    float* s_nB    = s_nA + NTHREADS * SCRP;
    float* s_zA    = s_nB + NTHREADS * SCRP;
    float* s_zB    = s_zA + NTHREADS * SCRP;

    const int tid = threadIdx.x;
    if (tid < 48)  s_wih[tid] = pk2(wih[2 * tid], wih[2 * tid + 1]);
    if (tid < 32)  s_brz[tid] = bih[tid] + bhh[tid];
    if (tid >= 32 && tid < 48) {
        int k = tid - 32;
        s_bin[k] = bih[32 + k];
        s_bhn[k] = bhh[32 + k];
    }
    if (tid >= 48 && tid < 56) {
        int p = tid - 48;
        s_wsumP[p] = pk2(wsum[2 * p], wsum[2 * p + 1]);
        s_wcarP[p] = pk2(wcar[2 * p], wcar[2 * p + 1]);
    }
    if (tid == 56) { s_bs[0] = bsum[0]; s_bs[1] = bcar[0]; }
    for (int i = tid; i < 384; i += NTHREADS) {
        int j = i / 8, q = i % 8;
        s_whh[i] = pk2(whh[j * 16 + 2 * q], whh[j * 16 + 2 * q + 1]);
    }
    __syncthreads();

    const size_t gt = (size_t)blockIdx.x * NTHREADS + tid;
    const size_t b0 = 2 * gt;                  // elems b0, b0+1 per thread

    u64 hA[8], hB[8];                          // packed (h_2p, h_2p+1)
#pragma unroll
    for (int p = 0; p < 8; p++) { hA[p] = 0ull; hB[p] = 0ull; }

    float* outH = out;
    float* outS = out + 67108864ULL;   // + B*T*H
    float* outC = out + 71303168ULL;   // + B*T
    float* outO = out + 72351744ULL;   // + B
    const u64 NEG1 = 0xBF800000BF800000ull;
    const u64 ZERO = 0ull;
    const int scr = tid * SCRP;

#pragma unroll 1
    for (int t = 0; t < 4; t++) {
        float2 xvA = *(const float2*)(x + b0 * 8 + 2 * t);
        float2 xvB = *(const float2*)(x + (b0 + 1) * 8 + 2 * t);
        u64 pxA = pk2(xvA.x, xvA.y);
        u64 pxB = pk2(xvB.x, xvB.y);

        // Gate pass: rolled. Weight LDS (broadcast) feeds BOTH elements.
#pragma unroll 1
        for (int k = 0; k < 16; k++) {
            const int jr = k, jz = 16 + k, jn = 32 + k;
            u64 wiR = s_wih[jr], wiZ = s_wih[jz], wiN = s_wih[jn];
            u64 arA = f2fma(pxA, wiR, ZERO), arB = f2fma(pxB, wiR, ZERO);
            u64 azA = f2fma(pxA, wiZ, ZERO), azB = f2fma(pxB, wiZ, ZERO);
            u64 iNA = f2fma(pxA, wiN, ZERO), iNB = f2fma(pxB, wiN, ZERO);
            u64 hNA = ZERO, hNB = ZERO;
            const ulonglong2* wr = (const ulonglong2*)&s_whh[jr * 8];
            const ulonglong2* wz = (const ulonglong2*)&s_whh[jz * 8];
            const ulonglong2* wn = (const ulonglong2*)&s_whh[jn * 8];
#pragma unroll 2
            for (int q = 0; q < 4; q++) {
                ulonglong2 a = wr[q];
                ulonglong2 c = wz[q];
                ulonglong2 e = wn[q];
                arA = f2fma(hA[2 * q],     a.x, arA);
                arB = f2fma(hB[2 * q],     a.x, arB);
                azA = f2fma(hA[2 * q],     c.x, azA);
                azB = f2fma(hB[2 * q],     c.x, azB);
                hNA = f2fma(hA[2 * q],     e.x, hNA);
                hNB = f2fma(hB[2 * q],     e.x, hNB);
                arA = f2fma(hA[2 * q + 1], a.y, arA);
                arB = f2fma(hB[2 * q + 1], a.y, arB);
                azA = f2fma(hA[2 * q + 1], c.y, azA);
                azB = f2fma(hB[2 * q + 1], c.y, azB);
                hNA = f2fma(hA[2 * q + 1], e.y, hNA);
                hNB = f2fma(hB[2 * q + 1], e.y, hNB);
            }
            float brz_r = s_brz[jr], brz_z = s_brz[jz];
            float b_in = s_bin[k],  b_hn = s_bhn[k];
            float rA = sigmoidf_(hsum(arA) + brz_r);
            float rB = sigmoidf_(hsum(arB) + brz_r);
            float zAv = sigmoidf_(hsum(azA) + brz_z);
            float zBv = sigmoidf_(hsum(azB) + brz_z);
            float nAv = tanhf_(fmaf(rA, hsum(hNA) + b_hn, hsum(iNA) + b_in));
            float nBv = tanhf_(fmaf(rB, hsum(hNB) + b_hn, hsum(iNB) + b_in));
            s_nA[scr + k] = nAv;
            s_nB[scr + k] = nBv;
            s_zA[scr + k] = zAv;
            s_zB[scr + k] = zBv;
        }

        // Update pass: LDS.64 yields packed (v_2p, v_2p+1) directly.
        u64 stA = ZERO, stB = ZERO;
#pragma unroll
        for (int p = 0; p < 8; p++) {
            u64 nnA = *(const u64*)&s_nA[scr + 2 * p];
            u64 nnB = *(const u64*)&s_nB[scr + 2 * p];
            u64 zzA = *(const u64*)&s_zA[scr + 2 * p];
            u64 zzB = *(const u64*)&s_zB[scr + 2 * p];
            hA[p] = f2fma(zzA, f2fma(nnA, NEG1, hA[p]), nnA);
            hB[p] = f2fma(zzB, f2fma(nnB, NEG1, hB[p]), nnB);
            stA = f2fma(hA[p], s_wsumP[p], stA);
            stB = f2fma(hB[p], s_wsumP[p], stB);
        }
        float slA = s_bs[0] + hsum(stA);
        float slB = s_bs[0] + hsum(stB);

        outS[b0 * 4 + t] = slA;
        outS[(b0 + 1) * 4 + t] = slB;
        outO[b0 * 5 + t] = slA;
        outO[(b0 + 1) * 5 + t] = slB;

        ulonglong2* phA = (ulonglong2*)(outH + (b0 * 4 + (size_t)t) * 16);
        phA[0] = make_ulonglong2(hA[0], hA[1]);
        phA[1] = make_ulonglong2(hA[2], hA[3]);
        phA[2] = make_ulonglong2(hA[4], hA[5]);
        phA[3] = make_ulonglong2(hA[6], hA[7]);
        ulonglong2* phB = (ulonglong2*)(outH + ((b0 + 1) * 4 + (size_t)t) * 16);
        phB[0] = make_ulonglong2(hB[0], hB[1]);
        phB[1] = make_ulonglong2(hB[2], hB[3]);
        phB[2] = make_ulonglong2(hB[4], hB[5]);
        phB[3] = make_ulonglong2(hB[6], hB[7]);
    }

    // carry logits from h_last
    u64 ccA = ZERO, ccB = ZERO;
#pragma unroll
    for (int p = 0; p < 8; p++) {
        ccA = f2fma(hA[p], s_wcarP[p], ccA);
        ccB = f2fma(hB[p], s_wcarP[p], ccB);
    }
    float cA = s_bs[1] + hsum(ccA);
    float cB = s_bs[1] + hsum(ccB);

    outC[b0] = cA;
    outC[b0 + 1] = cB;
    outO[b0 * 5 + 4] = cA;
    outO[(b0 + 1) * 5 + 4] = cB;
}

extern "C" void kernel_launch(void* const* d_in, const int* in_sizes, int n_in,
                              void* d_out, int out_size) {
    const float* x    = (const float*)d_in[0];
    const float* wih  = (const float*)d_in[1];
    const float* whh  = (const float*)d_in[2];
    const float* bih  = (const float*)d_in[3];
    const float* bhh  = (const float*)d_in[4];
    const float* wsum = (const float*)d_in[5];
    const float* bsum = (const float*)d_in[6];
    const float* wcar = (const float*)d_in[7];
    const float* bcar = (const float*)d_in[8];
    float* out = (float*)d_out;

    // weights 448*8 + biases (68 floats) + 4 scratch arrays of 256*18 floats
    const int smem_bytes = 448 * 8 + 68 * 4 + 4 * NTHREADS * SCRP * 4;  // 77584
    cudaFuncSetAttribute(gru_adder_kernel,
                         cudaFuncAttributeMaxDynamicSharedMemorySize, smem_bytes);
    gru_adder_kernel<<<GRID_BLOCKS, NTHREADS, smem_bytes>>>(
        x, wih, whh, bih, bhh, wsum, bsum, wcar, bcar, out);
}

// round 7
// speedup vs baseline: 2.1616x; 2.1616x over previous
#include <cuda_runtime.h>

typedef unsigned long long u64;

#define NTHREADS 256
#define GRID_BLOCKS 4096   // 1048576 elems / 256, one elem per thread
#define SCR_PITCH 257      // odd pitch -> conflict-free [k][tid] access

// ---------- packed f32x2 + approx-math helpers ----------
__device__ __forceinline__ u64 f2fma(u64 a, u64 b, u64 c) {
    u64 d; asm("fma.rn.f32x2 %0, %1, %2, %3;" : "=l"(d) : "l"(a), "l"(b), "l"(c)); return d;
}
__device__ __forceinline__ u64 pk2(float lo, float hi) {
    u64 d; asm("mov.b64 %0, {%1,%2};" : "=l"(d) : "f"(lo), "f"(hi)); return d;
}
__device__ __forceinline__ float hsum(u64 a) {   // lo + hi
    float lo, hi;
    asm("mov.b64 {%0,%1}, %2;" : "=f"(lo), "=f"(hi) : "l"(a));
    return lo + hi;
}
__device__ __forceinline__ float ex2f(float x) {
    float y; asm("ex2.approx.f32 %0, %1;" : "=f"(y) : "f"(x)); return y;
}
__device__ __forceinline__ float rcpf(float x) {
    float y; asm("rcp.approx.f32 %0, %1;" : "=f"(y) : "f"(x)); return y;
}
__device__ __forceinline__ float sigmoidf_(float a) {
    return rcpf(1.0f + ex2f(-1.4426950408889634f * a));
}
__device__ __forceinline__ float tanhf_(float a) {
    return fmaf(2.0f, rcpf(1.0f + ex2f(-2.8853900817779268f * a)), -1.0f);
}

// ---------- kernel ----------
// B=1048576, T=4, I=2, H=16
// out layout: [hidden_table B*T*H][sum_logits B*T][carry B][output_logits B*5]

__global__ __launch_bounds__(NTHREADS, 3)   // 85-reg budget, 24 warps/SM
void gru_adder_kernel(const float* __restrict__ x,
                      const float* __restrict__ wih,   // [48,2]
                      const float* __restrict__ whh,   // [48,16]
                      const float* __restrict__ bih,   // [48]
                      const float* __restrict__ bhh,   // [48]
                      const float* __restrict__ wsum,  // [1,16]
                      const float* __restrict__ bsum,  // [1]
                      const float* __restrict__ wcar,  // [1,16]
                      const float* __restrict__ bcar,  // [1]
                      float* __restrict__ out)
{
    // Thread-invariant weights (broadcast LDS) + per-thread gate scratch.
    __shared__ __align__(16) u64   s_wih[48];     // (wih[j][0], wih[j][1])
    __shared__ __align__(16) u64   s_whh[384];    // [j][q] = (whh[j][2q], whh[j][2q+1])
    __shared__ __align__(16) u64   s_wsumP[8];    // (wsum[2p], wsum[2p+1])
    __shared__ __align__(16) u64   s_wcarP[8];
    __shared__ __align__(16) u64   s_brzP[32];    // (b_ih[j]+b_hh[j], 0) r,z rows
    __shared__ __align__(16) u64   s_binP[16];    // (b_ih[32+k], 0)
    __shared__ __align__(16) u64   s_bhnP[16];    // (b_hh[32+k], 0)
    __shared__ float s_bs[2];                     // bsum, bcarry
    __shared__ float s_nscr[16 * SCR_PITCH];      // per-thread n_k scratch
    __shared__ float s_zscr[16 * SCR_PITCH];      // per-thread z_k scratch

    const int tid = threadIdx.x;
    if (tid < 48)  s_wih[tid] = pk2(wih[2 * tid], wih[2 * tid + 1]);
    if (tid < 32)  s_brzP[tid] = pk2(bih[tid] + bhh[tid], 0.0f);
    if (tid >= 32 && tid < 48) {
        int k = tid - 32;
        s_binP[k] = pk2(bih[32 + k], 0.0f);
        s_bhnP[k] = pk2(bhh[32 + k], 0.0f);
    }
    if (tid >= 48 && tid < 56) {
        int p = tid - 48;
        s_wsumP[p] = pk2(wsum[2 * p], wsum[2 * p + 1]);
        s_wcarP[p] = pk2(wcar[2 * p], wcar[2 * p + 1]);
    }
    if (tid == 56) { s_bs[0] = bsum[0]; s_bs[1] = bcar[0]; }
    for (int i = tid; i < 384; i += NTHREADS) {
        int j = i / 8, q = i % 8;
        s_whh[i] = pk2(whh[j * 16 + 2 * q], whh[j * 16 + 2 * q + 1]);
    }
    __syncthreads();

    const size_t b = (size_t)blockIdx.x * NTHREADS + tid;  // one elem per thread

    u64 h[8];                          // packed (h_2p, h_2p+1); constant-indexed only
#pragma unroll
    for (int p = 0; p < 8; p++) h[p] = 0ull;

    float* outH = out;
    float* outS = out + 67108864ULL;   // + B*T*H
    float* outC = out + 71303168ULL;   // + B*T
    float* outO = out + 72351744ULL;   // + B
    const u64 NEG1 = 0xBF800000BF800000ull;  // (-1.0f, -1.0f)
    const u64 ZERO = 0ull;

#pragma unroll 1
    for (int t = 0; t < 4; t++) {
        // x for this step: 8B load, L1-resident after first step
        float2 xv = *(const float2*)(x + b * 8 + 2 * t);
        u64 pxt = pk2(xv.x, xv.y);

        // Gate pass: rolled (unroll 1 -> small scheduling window, no spill).
        // Biases pre-folded into the packed accumulator init (lo lane).
#pragma unroll 1
        for (int k = 0; k < 16; k++) {
            const int jr = k, jz = 16 + k, jn = 32 + k;
            u64 ar = f2fma(pxt, s_wih[jr], s_brzP[jr]);
            u64 az = f2fma(pxt, s_wih[jz], s_brzP[jz]);
            u64 iN = f2fma(pxt, s_wih[jn], s_binP[k]);
            u64 hN = s_bhnP[k];
            const ulonglong2* wr = (const ulonglong2*)&s_whh[jr * 8];
            const ulonglong2* wz = (const ulonglong2*)&s_whh[jz * 8];
            const ulonglong2* wn = (const ulonglong2*)&s_whh[jn * 8];
#pragma unroll
            for (int q = 0; q < 4; q++) {
                ulonglong2 a = wr[q];
                ulonglong2 c = wz[q];
                ulonglong2 e = wn[q];
                ar = f2fma(h[2 * q],     a.x, ar);
                az = f2fma(h[2 * q],     c.x, az);
                hN = f2fma(h[2 * q],     e.x, hN);
                ar = f2fma(h[2 * q + 1], a.y, ar);
                az = f2fma(h[2 * q + 1], c.y, az);
                hN = f2fma(h[2 * q + 1], e.y, hN);
            }
            float r = sigmoidf_(hsum(ar));
            float z = sigmoidf_(hsum(az));
            float n = tanhf_(fmaf(r, hsum(hN), hsum(iN)));
            s_nscr[k * SCR_PITCH + tid] = n;
            s_zscr[k * SCR_PITCH + tid] = z;
        }

        // Update pass: read back own-lane scratch, update packed h, sum logit.
        u64 stp = ZERO;
#pragma unroll
        for (int p = 0; p < 8; p++) {
            float n0 = s_nscr[(2 * p)     * SCR_PITCH + tid];
            float n1 = s_nscr[(2 * p + 1) * SCR_PITCH + tid];
            float z0 = s_zscr[(2 * p)     * SCR_PITCH + tid];
            float z1 = s_zscr[(2 * p + 1) * SCR_PITCH + tid];
            u64 nn = pk2(n0, n1);
            u64 zz = pk2(z0, z1);
            h[p] = f2fma(zz, f2fma(nn, NEG1, h[p]), nn);   // n + z*(h-n)
            stp  = f2fma(h[p], s_wsumP[p], stp);
        }
        float sl = s_bs[0] + hsum(stp);

        outS[b * 4 + t] = sl;
        outO[b * 5 + t] = sl;

        ulonglong2* ph = (ulonglong2*)(outH + (b * 4 + (size_t)t) * 16);
        ph[0] = make_ulonglong2(h[0], h[1]);
        ph[1] = make_ulonglong2(h[2], h[3]);
        ph[2] = make_ulonglong2(h[4], h[5]);
        ph[3] = make_ulonglong2(h[6], h[7]);
    }

    // carry logit from h_last (packed)
    u64 cc = ZERO;
#pragma unroll
    for (int p = 0; p < 8; p++) cc = f2fma(h[p], s_wcarP[p], cc);
    float c = s_bs[1] + hsum(cc);

    outC[b]         = c;
    outO[b * 5 + 4] = c;
}

extern "C" void kernel_launch(void* const* d_in, const int* in_sizes, int n_in,
                              void* d_out, int out_size) {
    const float* x    = (const float*)d_in[0];
    const float* wih  = (const float*)d_in[1];
    const float* whh  = (const float*)d_in[2];
    const float* bih  = (const float*)d_in[3];
    const float* bhh  = (const float*)d_in[4];
    const float* wsum = (const float*)d_in[5];
    const float* bsum = (const float*)d_in[6];
    const float* wcar = (const float*)d_in[7];
    const float* bcar = (const float*)d_in[8];
    float* out = (float*)d_out;
    gru_adder_kernel<<<GRID_BLOCKS, NTHREADS>>>(x, wih, whh, bih, bhh,
                                                wsum, bsum, wcar, bcar, out);
}

// round 8
// speedup vs baseline: 2.5376x; 1.1739x over previous
#include <cuda_runtime.h>

typedef unsigned long long u64;

#define NTHREADS 256
#define GRID_BLOCKS 2048   // 1048576 elems / (2 per thread * 256)
#define SCR_PITCH 257      // [k][257+tid] -> conflict-free scalar scratch

// ---------- packed f32x2 + approx-math helpers ----------
__device__ __forceinline__ u64 f2fma(u64 a, u64 b, u64 c) {
    u64 d; asm("fma.rn.f32x2 %0, %1, %2, %3;" : "=l"(d) : "l"(a), "l"(b), "l"(c)); return d;
}
__device__ __forceinline__ u64 pk2(float lo, float hi) {
    u64 d; asm("mov.b64 %0, {%1,%2};" : "=l"(d) : "f"(lo), "f"(hi)); return d;
}
__device__ __forceinline__ float hsum(u64 a) {   // lo + hi
    float lo, hi;
    asm("mov.b64 {%0,%1}, %2;" : "=f"(lo), "=f"(hi) : "l"(a));
    return lo + hi;
}
__device__ __forceinline__ float ex2f(float x) {
    float y; asm("ex2.approx.f32 %0, %1;" : "=f"(y) : "f"(x)); return y;
}
__device__ __forceinline__ float rcpf(float x) {
    float y; asm("rcp.approx.f32 %0, %1;" : "=f"(y) : "f"(x)); return y;
}
__device__ __forceinline__ float sigmoidf_(float a) {
    return rcpf(1.0f + ex2f(-1.4426950408889634f * a));
}
__device__ __forceinline__ float tanhf_(float a) {
    return fmaf(2.0f, rcpf(1.0f + ex2f(-2.8853900817779268f * a)), -1.0f);
}

// ---------- kernel ----------
// B=1048576, T=4, I=2, H=16
// out layout: [hidden_table B*T*H][sum_logits B*T][carry B][output_logits B*5]

__global__ __launch_bounds__(NTHREADS, 2)
void gru_adder_kernel(const float* __restrict__ x,
                      const float* __restrict__ wih,   // [48,2]
                      const float* __restrict__ whh,   // [48,16]
                      const float* __restrict__ bih,   // [48]
                      const float* __restrict__ bhh,   // [48]
                      const float* __restrict__ wsum,  // [1,16]
                      const float* __restrict__ bsum,  // [1]
                      const float* __restrict__ wcar,  // [1,16]
                      const float* __restrict__ bcar,  // [1]
                      float* __restrict__ out)
{
    extern __shared__ __align__(16) char smem_raw[];
    u64*   s_whh   = (u64*)smem_raw;          // 384: [j][q]=(whh[j][2q], whh[j][2q+1])
    u64*   s_kblk  = s_whh + 384;             // 48*8: per-k constant block (64B)
    u64*   s_wsumP = s_kblk + 384;            // 8
    u64*   s_wcarP = s_wsumP + 8;             // 8
    float* s_bs    = (float*)(s_wcarP + 8);   // 2 (+pad)
    float* s_nA    = s_bs + 4;                // [k][257+tid]
    float* s_nB    = s_nA + 16 * SCR_PITCH;
    float* s_zA    = s_nB + 16 * SCR_PITCH;
    float* s_zB    = s_zA + 16 * SCR_PITCH;

    const int tid = threadIdx.x;
    // per-k constant block: {wihR, wihZ, wihN, brzR, brzZ, binN, bhnN, pad}
    if (tid < 16) {
        int k = tid;
        s_kblk[k * 8 + 0] = pk2(wih[2 * k],            wih[2 * k + 1]);
        s_kblk[k * 8 + 1] = pk2(wih[2 * (16 + k)],     wih[2 * (16 + k) + 1]);
        s_kblk[k * 8 + 2] = pk2(wih[2 * (32 + k)],     wih[2 * (32 + k) + 1]);
        s_kblk[k * 8 + 3] = pk2(bih[k] + bhh[k],           0.0f);
        s_kblk[k * 8 + 4] = pk2(bih[16 + k] + bhh[16 + k], 0.0f);
        s_kblk[k * 8 + 5] = pk2(bih[32 + k],               0.0f);
        s_kblk[k * 8 + 6] = pk2(bhh[32 + k],               0.0f);
        s_kblk[k * 8 + 7] = 0ull;
    }
    if (tid >= 16 && tid < 24) {
        int p = tid - 16;
        s_wsumP[p] = pk2(wsum[2 * p], wsum[2 * p + 1]);
        s_wcarP[p] = pk2(wcar[2 * p], wcar[2 * p + 1]);
    }
    if (tid == 24) { s_bs[0] = bsum[0]; s_bs[1] = bcar[0]; }
    for (int i = tid; i < 384; i += NTHREADS) {
        int j = i / 8, q = i % 8;
        s_whh[i] = pk2(whh[j * 16 + 2 * q], whh[j * 16 + 2 * q + 1]);
    }
    __syncthreads();

    const size_t gt = (size_t)blockIdx.x * NTHREADS + tid;
    const size_t b0 = 2 * gt;                  // elems b0, b0+1 per thread

    u64 hA[8], hB[8];                          // packed (h_2p, h_2p+1)
#pragma unroll
    for (int p = 0; p < 8; p++) { hA[p] = 0ull; hB[p] = 0ull; }

    float* outH = out;
    float* outS = out + 67108864ULL;   // + B*T*H
    float* outC = out + 71303168ULL;   // + B*T
    float* outO = out + 72351744ULL;   // + B
    const u64 NEG1 = 0xBF800000BF800000ull;
    const u64 ZERO = 0ull;

#pragma unroll 1
    for (int t = 0; t < 4; t++) {
        float2 xvA = *(const float2*)(x + b0 * 8 + 2 * t);
        float2 xvB = *(const float2*)(x + (b0 + 1) * 8 + 2 * t);
        u64 pxA = pk2(xvA.x, xvA.y);
        u64 pxB = pk2(xvB.x, xvB.y);

        // Gate pass: rolled. 16 broadcast LDS.128 per k feed BOTH elements.
#pragma unroll 1
        for (int k = 0; k < 16; k++) {
            const ulonglong2* kb = (const ulonglong2*)&s_kblk[k * 8];
            ulonglong2 kb0 = kb[0];   // (wihR, wihZ)
            ulonglong2 kb1 = kb[1];   // (wihN, brzR)
            ulonglong2 kb2 = kb[2];   // (brzZ, binN)
            ulonglong2 kb3 = kb[3];   // (bhnN, pad)
            u64 arA = f2fma(pxA, kb0.x, kb1.y);
            u64 arB = f2fma(pxB, kb0.x, kb1.y);
            u64 azA = f2fma(pxA, kb0.y, kb2.x);
            u64 azB = f2fma(pxB, kb0.y, kb2.x);
            u64 iNA = f2fma(pxA, kb1.x, kb2.y);
            u64 iNB = f2fma(pxB, kb1.x, kb2.y);
            u64 hNA = kb3.x;
            u64 hNB = kb3.x;
            const ulonglong2* wr = (const ulonglong2*)&s_whh[k * 8];
            const ulonglong2* wz = (const ulonglong2*)&s_whh[(16 + k) * 8];
            const ulonglong2* wn = (const ulonglong2*)&s_whh[(32 + k) * 8];
#pragma unroll
            for (int q = 0; q < 4; q++) {
                ulonglong2 a = wr[q];
                ulonglong2 c = wz[q];
                ulonglong2 e = wn[q];
                arA = f2fma(hA[2 * q],     a.x, arA);
                arB = f2fma(hB[2 * q],     a.x, arB);
                azA = f2fma(hA[2 * q],     c.x, azA);
                azB = f2fma(hB[2 * q],     c.x, azB);
                hNA = f2fma(hA[2 * q],     e.x, hNA);
                hNB = f2fma(hB[2 * q],     e.x, hNB);
                arA = f2fma(hA[2 * q + 1], a.y, arA);
                arB = f2fma(hB[2 * q + 1], a.y, arB);
                azA = f2fma(hA[2 * q + 1], c.y, azA);
                azB = f2fma(hB[2 * q + 1], c.y, azB);
                hNA = f2fma(hA[2 * q + 1], e.y, hNA);
                hNB = f2fma(hB[2 * q + 1], e.y, hNB);
            }
            float rA = sigmoidf_(hsum(arA));
            float rB = sigmoidf_(hsum(arB));
            float zA = sigmoidf_(hsum(azA));
            float zB = sigmoidf_(hsum(azB));
            float nA = tanhf_(fmaf(rA, hsum(hNA), hsum(iNA)));
            float nB = tanhf_(fmaf(rB, hsum(hNB), hsum(iNB)));
            s_nA[k * SCR_PITCH + tid] = nA;
            s_nB[k * SCR_PITCH + tid] = nB;
            s_zA[k * SCR_PITCH + tid] = zA;
            s_zB[k * SCR_PITCH + tid] = zB;
        }

        // Update pass: conflict-free scalar readback, packed h update.
        u64 stA = ZERO, stB = ZERO;
#pragma unroll
        for (int p = 0; p < 8; p++) {
            u64 nnA = pk2(s_nA[(2 * p) * SCR_PITCH + tid], s_nA[(2 * p + 1) * SCR_PITCH + tid]);
            u64 zzA = pk2(s_zA[(2 * p) * SCR_PITCH + tid], s_zA[(2 * p + 1) * SCR_PITCH + tid]);
            u64 nnB = pk2(s_nB[(2 * p) * SCR_PITCH + tid], s_nB[(2 * p + 1) * SCR_PITCH + tid]);
            u64 zzB = pk2(s_zB[(2 * p) * SCR_PITCH + tid], s_zB[(2 * p + 1) * SCR_PITCH + tid]);
            hA[p] = f2fma(zzA, f2fma(nnA, NEG1, hA[p]), nnA);
            hB[p] = f2fma(zzB, f2fma(nnB, NEG1, hB[p]), nnB);
            stA = f2fma(hA[p], s_wsumP[p], stA);
            stB = f2fma(hB[p], s_wsumP[p], stB);
        }
        float slA = s_bs[0] + hsum(stA);
        float slB = s_bs[0] + hsum(stB);

        outS[b0 * 4 + t]       = slA;
        outS[(b0 + 1) * 4 + t] = slB;
        outO[b0 * 5 + t]       = slA;
        outO[(b0 + 1) * 5 + t] = slB;

        ulonglong2* phA = (ulonglong2*)(outH + (b0 * 4 + (size_t)t) * 16);
        phA[0] = make_ulonglong2(hA[0], hA[1]);
        phA[1] = make_ulonglong2(hA[2], hA[3]);
        phA[2] = make_ulonglong2(hA[4], hA[5]);
        phA[3] = make_ulonglong2(hA[6], hA[7]);
        ulonglong2* phB = (ulonglong2*)(outH + ((b0 + 1) * 4 + (size_t)t) * 16);
        phB[0] = make_ulonglong2(hB[0], hB[1]);
        phB[1] = make_ulonglong2(hB[2], hB[3]);
        phB[2] = make_ulonglong2(hB[4], hB[5]);
        phB[3] = make_ulonglong2(hB[6], hB[7]);
    }

    // carry logits from h_last
    u64 ccA = ZERO, ccB = ZERO;
#pragma unroll
    for (int p = 0; p < 8; p++) {
        ccA = f2fma(hA[p], s_wcarP[p], ccA);
        ccB = f2fma(hB[p], s_wcarP[p], ccB);
    }
    float cA = s_bs[1] + hsum(ccA);
    float cB = s_bs[1] + hsum(ccB);

    outC[b0]               = cA;
    outC[b0 + 1]           = cB;
    outO[b0 * 5 + 4]       = cA;
    outO[(b0 + 1) * 5 + 4] = cB;
}

extern "C" void kernel_launch(void* const* d_in, const int* in_sizes, int n_in,
                              void* d_out, int out_size) {
    const float* x    = (const float*)d_in[0];
    const float* wih  = (const float*)d_in[1];
    const float* whh  = (const float*)d_in[2];
    const float* bih  = (const float*)d_in[3];
    const float* bhh  = (const float*)d_in[4];
    const float* wsum = (const float*)d_in[5];
    const float* bsum = (const float*)d_in[6];
    const float* wcar = (const float*)d_in[7];
    const float* bcar = (const float*)d_in[8];
    float* out = (float*)d_out;

    // (384+384+8+8) u64 + 4 pad floats + 4 scratch arrays of 16*257 floats
    const int smem_bytes = 784 * 8 + 4 * 4 + 4 * 16 * SCR_PITCH * 4;  // 72,080
    cudaFuncSetAttribute(gru_adder_kernel,
                         cudaFuncAttributeMaxDynamicSharedMemorySize, smem_bytes);
    gru_adder_kernel<<<GRID_BLOCKS, NTHREADS, smem_bytes>>>(
        x, wih, whh, bih, bhh, wsum, bsum, wcar, bcar, out);
}

// round 10
// speedup vs baseline: 2.5579x; 1.0080x over previous
#include <cuda_runtime.h>

typedef unsigned long long u64;

#define NTHREADS 256
#define GRID_BLOCKS 2048   // 1048576 elems / (2 per thread * 256)

// ---------- packed f32x2 + approx-math helpers ----------
__device__ __forceinline__ u64 f2fma(u64 a, u64 b, u64 c) {
    u64 d; asm("fma.rn.f32x2 %0, %1, %2, %3;" : "=l"(d) : "l"(a), "l"(b), "l"(c)); return d;
}
__device__ __forceinline__ u64 pk2(float lo, float hi) {
    u64 d; asm("mov.b64 %0, {%1,%2};" : "=l"(d) : "f"(lo), "f"(hi)); return d;
}
__device__ __forceinline__ void up2(u64 a, float& lo, float& hi) {
    asm("mov.b64 {%0,%1}, %2;" : "=f"(lo), "=f"(hi) : "l"(a));
}
__device__ __forceinline__ float hsum(u64 a) {   // lo + hi
    float lo, hi; up2(a, lo, hi); return lo + hi;
}
__device__ __forceinline__ float ex2f(float x) {
    float y; asm("ex2.approx.f32 %0, %1;" : "=f"(y) : "f"(x)); return y;
}
__device__ __forceinline__ float rcpf(float x) {
    float y; asm("rcp.approx.f32 %0, %1;" : "=f"(y) : "f"(x)); return y;
}
__device__ __forceinline__ float sigmoidf_(float a) {
    return rcpf(1.0f + ex2f(-1.4426950408889634f * a));
}
__device__ __forceinline__ float tanhf_(float a) {
    return fmaf(2.0f, rcpf(1.0f + ex2f(-2.8853900817779268f * a)), -1.0f);
}

// ---------- kernel ----------
// B=1048576, T=4, I=2, H=16
// out layout: [hidden_table B*T*H][sum_logits B*T][carry B][output_logits B*5]

__global__ __launch_bounds__(NTHREADS, 2)
void gru_adder_kernel(const float* __restrict__ x,
                      const float* __restrict__ wih,   // [48,2]
                      const float* __restrict__ whh,   // [48,16]
                      const float* __restrict__ bih,   // [48]
                      const float* __restrict__ bhh,   // [48]
                      const float* __restrict__ wsum,  // [1,16]
                      const float* __restrict__ bsum,  // [1]
                      const float* __restrict__ wcar,  // [1,16]
                      const float* __restrict__ bcar,  // [1]
                      float* __restrict__ out)
{
    extern __shared__ __align__(16) char smem_raw[];
    u64*   s_whh   = (u64*)smem_raw;          // 384: [j][q]=(whh[j][2q], whh[j][2q+1])
    u64*   s_kblk  = s_whh + 384;             // 48*8: per-k constant block (64B)
    u64*   s_wsumP = s_kblk + 384;            // 8
    u64*   s_wcarP = s_wsumP + 8;             // 8
    float* s_bs    = (float*)(s_wcarP + 8);   // 2 (+pad to 16B)
    u64*   s_nAB   = (u64*)(s_bs + 4);        // [k][tid] packed (nA_k, nB_k)
    u64*   s_zAB   = s_nAB + 16 * NTHREADS;   // [k][tid] packed (zA_k, zB_k)

    const int tid = threadIdx.x;
    // per-k constant block: {wihR, wihZ, wihN, brzR, brzZ, binN, bhnN, pad}
    if (tid < 16) {
        int k = tid;
        s_kblk[k * 8 + 0] = pk2(wih[2 * k],            wih[2 * k + 1]);
        s_kblk[k * 8 + 1] = pk2(wih[2 * (16 + k)],     wih[2 * (16 + k) + 1]);
        s_kblk[k * 8 + 2] = pk2(wih[2 * (32 + k)],     wih[2 * (32 + k) + 1]);
        s_kblk[k * 8 + 3] = pk2(bih[k] + bhh[k],           0.0f);
        s_kblk[k * 8 + 4] = pk2(bih[16 + k] + bhh[16 + k], 0.0f);
        s_kblk[k * 8 + 5] = pk2(bih[32 + k],               0.0f);
        s_kblk[k * 8 + 6] = pk2(bhh[32 + k],               0.0f);
        s_kblk[k * 8 + 7] = 0ull;
    }
    if (tid >= 16 && tid < 24) {
        int p = tid - 16;
        s_wsumP[p] = pk2(wsum[2 * p], wsum[2 * p + 1]);
        s_wcarP[p] = pk2(wcar[2 * p], wcar[2 * p + 1]);
    }
    if (tid == 24) { s_bs[0] = bsum[0]; s_bs[1] = bcar[0]; }
    for (int i = tid; i < 384; i += NTHREADS) {
        int j = i / 8, q = i % 8;
        s_whh[i] = pk2(whh[j * 16 + 2 * q], whh[j * 16 + 2 * q + 1]);
    }
    __syncthreads();

    const size_t gt = (size_t)blockIdx.x * NTHREADS + tid;
    const size_t b0 = 2 * gt;                  // elems b0, b0+1 per thread

    u64 hA[8], hB[8];                          // packed (h_2p, h_2p+1)
#pragma unroll
    for (int p = 0; p < 8; p++) { hA[p] = 0ull; hB[p] = 0ull; }

    float* outH = out;
    float* outS = out + 67108864ULL;   // + B*T*H
    float* outC = out + 71303168ULL;   // + B*T
    float* outO = out + 72351744ULL;   // + B
    const u64 NEG1 = 0xBF800000BF800000ull;
    const u64 ZERO = 0ull;

#pragma unroll 1
    for (int t = 0; t < 4; t++) {
        float2 xvA = *(const float2*)(x + b0 * 8 + 2 * t);
        float2 xvB = *(const float2*)(x + (b0 + 1) * 8 + 2 * t);
        u64 pxA = pk2(xvA.x, xvA.y);
        u64 pxB = pk2(xvB.x, xvB.y);

        // Gate pass: rolled. 16 broadcast LDS.128 per k feed BOTH elements.
        // Scratch writes packed as (elemA, elemB) u64 -> 2 STS.64 per k.
#pragma unroll 1
        for (int k = 0; k < 16; k++) {
            const ulonglong2* kb = (const ulonglong2*)&s_kblk[k * 8];
            ulonglong2 kb0 = kb[0];   // (wihR, wihZ)
            ulonglong2 kb1 = kb[1];   // (wihN, brzR)
            ulonglong2 kb2 = kb[2];   // (brzZ, binN)
            ulonglong2 kb3 = kb[3];   // (bhnN, pad)
            u64 arA = f2fma(pxA, kb0.x, kb1.y);
            u64 arB = f2fma(pxB, kb0.x, kb1.y);
            u64 azA = f2fma(pxA, kb0.y, kb2.x);
            u64 azB = f2fma(pxB, kb0.y, kb2.x);
            u64 iNA = f2fma(pxA, kb1.x, kb2.y);
            u64 iNB = f2fma(pxB, kb1.x, kb2.y);
            u64 hNA = kb3.x;
            u64 hNB = kb3.x;
            const ulonglong2* wr = (const ulonglong2*)&s_whh[k * 8];
            const ulonglong2* wz = (const ulonglong2*)&s_whh[(16 + k) * 8];
            const ulonglong2* wn = (const ulonglong2*)&s_whh[(32 + k) * 8];
#pragma unroll
            for (int q = 0; q < 4; q++) {
                ulonglong2 a = wr[q];
                ulonglong2 c = wz[q];
                ulonglong2 e = wn[q];
                arA = f2fma(hA[2 * q],     a.x, arA);
                arB = f2fma(hB[2 * q],     a.x, arB);
                azA = f2fma(hA[2 * q],     c.x, azA);
                azB = f2fma(hB[2 * q],     c.x, azB);
                hNA = f2fma(hA[2 * q],     e.x, hNA);
                hNB = f2fma(hB[2 * q],     e.x, hNB);
                arA = f2fma(hA[2 * q + 1], a.y, arA);
                arB = f2fma(hB[2 * q + 1], a.y, arB);
                azA = f2fma(hA[2 * q + 1], c.y, azA);
                azB = f2fma(hB[2 * q + 1], c.y, azB);
                hNA = f2fma(hA[2 * q + 1], e.y, hNA);
                hNB = f2fma(hB[2 * q + 1], e.y, hNB);
            }
            float rA = sigmoidf_(hsum(arA));
            float rB = sigmoidf_(hsum(arB));
            float zA = sigmoidf_(hsum(azA));
            float zB = sigmoidf_(hsum(azB));
            float nA = tanhf_(fmaf(rA, hsum(hNA), hsum(iNA)));
            float nB = tanhf_(fmaf(rB, hsum(hNB), hsum(iNB)));
            s_nAB[k * NTHREADS + tid] = pk2(nA, nB);
            s_zAB[k * NTHREADS + tid] = pk2(zA, zB);
        }

        // Update pass: 4 LDS.64 per p (vs 8 LDS.32), repack lanes via movs (ALU).
        u64 stA = ZERO, stB = ZERO;
#pragma unroll
        for (int p = 0; p < 8; p++) {
            u64 n0 = s_nAB[(2 * p)     * NTHREADS + tid];
            u64 n1 = s_nAB[(2 * p + 1) * NTHREADS + tid];
            u64 z0 = s_zAB[(2 * p)     * NTHREADS + tid];
            u64 z1 = s_zAB[(2 * p + 1) * NTHREADS + tid];
            float n0l, n0h, n1l, n1h, z0l, z0h, z1l, z1h;
            up2(n0, n0l, n0h); up2(n1, n1l, n1h);
            up2(z0, z0l, z0h); up2(z1, z1l, z1h);
            u64 nnA = pk2(n0l, n1l), nnB = pk2(n0h, n1h);
            u64 zzA = pk2(z0l, z1l), zzB = pk2(z0h, z1h);
            hA[p] = f2fma(zzA, f2fma(nnA, NEG1, hA[p]), nnA);
            hB[p] = f2fma(zzB, f2fma(nnB, NEG1, hB[p]), nnB);
            stA = f2fma(hA[p], s_wsumP[p], stA);
            stB = f2fma(hB[p], s_wsumP[p], stB);
        }
        float slA = s_bs[0] + hsum(stA);
        float slB = s_bs[0] + hsum(stB);

        outS[b0 * 4 + t]       = slA;
        outS[(b0 + 1) * 4 + t] = slB;
        outO[b0 * 5 + t]       = slA;
        outO[(b0 + 1) * 5 + t] = slB;

        ulonglong2* phA = (ulonglong2*)(outH + (b0 * 4 + (size_t)t) * 16);
        phA[0] = make_ulonglong2(hA[0], hA[1]);
        phA[1] = make_ulonglong2(hA[2], hA[3]);
        phA[2] = make_ulonglong2(hA[4], hA[5]);
        phA[3] = make_ulonglong2(hA[6], hA[7]);
        ulonglong2* phB = (ulonglong2*)(outH + ((b0 + 1) * 4 + (size_t)t) * 16);
        phB[0] = make_ulonglong2(hB[0], hB[1]);
        phB[1] = make_ulonglong2(hB[2], hB[3]);
        phB[2] = make_ulonglong2(hB[4], hB[5]);
        phB[3] = make_ulonglong2(hB[6], hB[7]);
    }

    // carry logits from h_last
    u64 ccA = ZERO, ccB = ZERO;
#pragma unroll
    for (int p = 0; p < 8; p++) {
        ccA = f2fma(hA[p], s_wcarP[p], ccA);
        ccB = f2fma(hB[p], s_wcarP[p], ccB);
    }
    float cA = s_bs[1] + hsum(ccA);
    float cB = s_bs[1] + hsum(ccB);

    outC[b0]               = cA;
    outC[b0 + 1]           = cB;
    outO[b0 * 5 + 4]       = cA;
    outO[(b0 + 1) * 5 + 4] = cB;
}

extern "C" void kernel_launch(void* const* d_in, const int* in_sizes, int n_in,
                              void* d_out, int out_size) {
    const float* x    = (const float*)d_in[0];
    const float* wih  = (const float*)d_in[1];
    const float* whh  = (const float*)d_in[2];
    const float* bih  = (const float*)d_in[3];
    const float* bhh  = (const float*)d_in[4];
    const float* wsum = (const float*)d_in[5];
    const float* bsum = (const float*)d_in[6];
    const float* wcar = (const float*)d_in[7];
    const float* bcar = (const float*)d_in[8];
    float* out = (float*)d_out;

    // (384+384+8+8) u64 + 4 pad floats + 2 scratch arrays of 16*256 u64
    const int smem_bytes = 784 * 8 + 4 * 4 + 2 * 16 * NTHREADS * 8;  // 71,824
    cudaFuncSetAttribute(gru_adder_kernel,
                         cudaFuncAttributeMaxDynamicSharedMemorySize, smem_bytes);
    gru_adder_kernel<<<GRID_BLOCKS, NTHREADS, smem_bytes>>>(
        x, wih, whh, bih, bhh, wsum, bsum, wcar, bcar, out);
}